// round 15
// baseline (speedup 1.0000x reference)
#include <cuda_runtime.h>
#include <cuda_fp16.h>
#include <cstdint>

#define LQ 2048
#define BB 8
#define DD 768
#define MROWS (BB * LQ)
#define ZB (2 * BB)                 // branch*8 + batch
#define QKSCALE 0.0360843918243516f

using f16 = __half;

// ---------------------------------------------------------------------------
// Scratch (device globals; allocation-free per harness rules)
// ---------------------------------------------------------------------------
__device__ __align__(16) f16   g_S[(size_t)ZB * LQ * LQ];     // 128MB exp-logits (unnormalized)
__device__ __align__(16) f16   g_q[(size_t)MROWS * DD];
__device__ __align__(16) f16   g_kv[(size_t)2 * MROWS * DD];
__device__ __align__(16) f16   g_kT[(size_t)2 * MROWS * DD];
__device__ __align__(16) f16   g_c[(size_t)2 * MROWS * DD];
__device__ __align__(16) f16   g_W[2 * DD * DD];
__device__ __align__(16) f16   g_y[(size_t)2 * MROWS * DD];   // conv out fp16, both branches
__device__ float g_rspart[(size_t)ZB * LQ * 16];              // softmax row partial sums
__device__ float g_rsinv[(size_t)ZB * LQ];                    // 1/rowsum
__device__ float g_part[2 * 2 * 128 * DD];                    // BN partials [br][sum|sq][128][768]
__device__ float g_stats[2 * 2 * DD];

// ---------------------------------------------------------------------------
// Helpers (baseline PTX only: ldmatrix / mma.sync / cp.async)
// ---------------------------------------------------------------------------
__device__ __forceinline__ uint32_t smem_u32(const void* p) {
    uint32_t a;
    asm("{ .reg .u64 t; cvta.to.shared.u64 t, %1; cvt.u32.u64 %0, t; }" : "=r"(a) : "l"(p));
    return a;
}
__device__ __forceinline__ void cp16(uint32_t saddr, const void* gaddr) {
    asm volatile("cp.async.cg.shared.global [%0], [%1], 16;" :: "r"(saddr), "l"(gaddr));
}
#define CP_COMMIT() asm volatile("cp.async.commit_group;" ::: "memory")
#define CP_WAIT0()  asm volatile("cp.async.wait_group 0;" ::: "memory")
#define CP_WAIT1()  asm volatile("cp.async.wait_group 1;" ::: "memory")

__device__ __forceinline__ void ldmat_x4(uint32_t& r0, uint32_t& r1, uint32_t& r2,
                                         uint32_t& r3, uint32_t addr) {
    asm volatile("ldmatrix.sync.aligned.m8n8.x4.shared.b16 {%0,%1,%2,%3}, [%4];"
                 : "=r"(r0), "=r"(r1), "=r"(r2), "=r"(r3) : "r"(addr));
}
__device__ __forceinline__ void mma16816(float* c, uint32_t a0, uint32_t a1,
                                         uint32_t a2, uint32_t a3,
                                         uint32_t b0, uint32_t b1) {
    asm volatile(
        "mma.sync.aligned.m16n8k16.row.col.f32.f16.f16.f32 "
        "{%0,%1,%2,%3}, {%4,%5,%6,%7}, {%8,%9}, {%0,%1,%2,%3};"
        : "+f"(c[0]), "+f"(c[1]), "+f"(c[2]), "+f"(c[3])
        : "r"(a0), "r"(a1), "r"(a2), "r"(a3), "r"(b0), "r"(b1));
}

__device__ __forceinline__ uint32_t sw_off(int row, int kbyte) {
    uint32_t off = (uint32_t)row * 128u + (uint32_t)kbyte;
    return off ^ ((off >> 3) & 0x70u);
}
__device__ __forceinline__ uint32_t pack_h(float a, float b) {
    __half2 h = __float22half2_rn(make_float2(a, b));
    return *(uint32_t*)&h;
}

// ---------------------------------------------------------------------------
// fp16 warp-MMA GEMM: C[m,n] = alpha * sum_k A[m,k]*B[n,k]
// Templated tile: NT=128 -> 128x128 CTA tile, 4 warps, 2 CTAs/SM.
//                 NT=256 -> 128x256 CTA tile, 8 warps, 1 CTA/SM.
// Warp tile always 64x64; K in 64-chunks; 3-stage cp.async pipeline.
// A batch index = z & amask; B/C batch index = z.
// OUTMODE 1: fp16 C (alpha; optional per-row scale from rowscale[]).
// OUTMODE 2: fp16 exp(alpha*acc) into Ch + per-row partial sums to aux.
// OUTMODE 3: fp16 C + deterministic per-channel BN partials into aux.
// ---------------------------------------------------------------------------
#define B_SM_OFF 16384

template<int NT>
__device__ __forceinline__ void stage_load(uint32_t sdst, const f16* __restrict__ A,
                                           const f16* __restrict__ B,
                                           int K, int k0, int t) {
    constexpr int TN = (NT == 128) ? 128 : 256;
#pragma unroll
    for (int i = 0; i < 1024 / NT; i++) {     // A: 128 rows x 8 chunks
        int idx = t + i * NT;
        int row = idx >> 3, ch = idx & 7;
        cp16(sdst + sw_off(row, ch * 16), A + (size_t)row * K + k0 + ch * 8);
    }
#pragma unroll
    for (int i = 0; i < TN * 8 / NT; i++) {   // B: TN rows x 8 chunks
        int idx = t + i * NT;
        int row = idx >> 3, ch = idx & 7;
        cp16(sdst + B_SM_OFF + sw_off(row, ch * 16), B + (size_t)row * K + k0 + ch * 8);
    }
}

template<int OUTMODE, int NT>
__global__ void __launch_bounds__(NT, 256 / NT)
mma_gemm(const f16* __restrict__ A, const f16* __restrict__ B,
         f16* __restrict__ Ch, const float* __restrict__ rowscale,
         float* __restrict__ aux,
         int K, int ldc, long sA, long sB, long sC, float alpha, int amask)
{
    constexpr int TN = (NT == 128) ? 128 : 256;
    constexpr uint32_t STAGE = 16384 + TN * 128;
    extern __shared__ __align__(1024) char smem[];
    const uint32_t sb = smem_u32(smem);
    const int t = threadIdx.x, lane = t & 31, wid = t >> 5;
    const int wm = wid & 1, wn = wid >> 1;          // 2x(NT/64/... ) warp grid, 64x64 tiles
    const int m0 = blockIdx.y * 128, n0 = blockIdx.x * TN, z = blockIdx.z;
    const int kiters = K >> 6;

    A += (size_t)(z & amask) * sA + (size_t)m0 * K;
    B += (size_t)z * sB + (size_t)n0 * K;

    float acc[4][8][4];
#pragma unroll
    for (int i = 0; i < 4; i++)
#pragma unroll
        for (int j = 0; j < 8; j++)
#pragma unroll
            for (int q = 0; q < 4; q++) acc[i][j][q] = 0.f;

    // ldmatrix lane-address components
    const int a_m_add = (lane & 7) + ((lane >> 3) & 1) * 8;
    const int a_k_add = ((lane >> 4) & 1) * 8;
    const int b_n_add = (lane & 7) + ((lane >> 4) << 3);
    const int b_k_add = ((lane >> 3) & 1) * 8;

    stage_load<NT>(sb, A, B, K, 0, t);
    CP_COMMIT();
    if (kiters > 1) {
        stage_load<NT>(sb + STAGE, A, B, K, 64, t);
        CP_COMMIT();
    }

    uint32_t cur = 0;
    for (int it = 0; it < kiters; it++) {
        if (it + 1 < kiters) { CP_WAIT1(); } else { CP_WAIT0(); }
        __syncthreads();
        if (it + 2 < kiters) {
            uint32_t nxt = cur + 2; if (nxt >= 3) nxt -= 3;
            stage_load<NT>(sb + nxt * STAGE, A, B, K, (it + 2) << 6, t);
            CP_COMMIT();
        }
        const uint32_t st = sb + cur * STAGE;

#pragma unroll
        for (int ks = 0; ks < 4; ks++) {
            const int kb = ks * 16;
            uint32_t ah[4][4];
#pragma unroll
            for (int tm = 0; tm < 4; tm++) {
                int m = wm * 64 + tm * 16 + a_m_add;
                uint32_t so = sw_off(m, (kb + a_k_add) * 2);
                ldmat_x4(ah[tm][0], ah[tm][1], ah[tm][2], ah[tm][3], st + so);
            }
            uint32_t bh[8][2];
#pragma unroll
            for (int tn2 = 0; tn2 < 4; tn2++) {
                int n = wn * 64 + tn2 * 16 + b_n_add;
                uint32_t so = sw_off(n, (kb + b_k_add) * 2);
                ldmat_x4(bh[tn2 * 2][0], bh[tn2 * 2][1],
                         bh[tn2 * 2 + 1][0], bh[tn2 * 2 + 1][1], st + B_SM_OFF + so);
            }
#pragma unroll
            for (int tm = 0; tm < 4; tm++)
#pragma unroll
                for (int tn = 0; tn < 8; tn++)
                    mma16816(acc[tm][tn], ah[tm][0], ah[tm][1], ah[tm][2], ah[tm][3],
                             bh[tn][0], bh[tn][1]);
        }
        cur = cur + 1; if (cur >= 3) cur -= 3;
    }

    const int gid = lane >> 2, tig = lane & 3;
    if (OUTMODE == 1) {
#pragma unroll
        for (int tm = 0; tm < 4; tm++) {
            const int r0 = m0 + wm * 64 + tm * 16 + gid;
            float rs0 = 1.f, rs1 = 1.f;
            if (rowscale) {
                rs0 = rowscale[(size_t)z * LQ + r0];
                rs1 = rowscale[(size_t)z * LQ + r0 + 8];
            }
#pragma unroll
            for (int tn = 0; tn < 8; tn++) {
                const int cN = n0 + wn * 64 + tn * 8 + tig * 2;
                float* a = acc[tm][tn];
                *(uint32_t*)(Ch + (size_t)z * sC + (size_t)r0 * ldc + cN) =
                    pack_h(a[0] * alpha * rs0, a[1] * alpha * rs0);
                *(uint32_t*)(Ch + (size_t)z * sC + (size_t)(r0 + 8) * ldc + cN) =
                    pack_h(a[2] * alpha * rs1, a[3] * alpha * rs1);
            }
        }
    } else if (OUTMODE == 2) {
        // exp epilogue + deterministic per-row partial sums (NT==128 only)
        float* rsum = (float*)smem;
        __syncthreads();
#pragma unroll
        for (int tm = 0; tm < 4; tm++) {
            const int rr = wm * 64 + tm * 16 + gid;
            const int r0 = m0 + rr;
            float sum0 = 0.f, sum1 = 0.f;
#pragma unroll
            for (int tn = 0; tn < 8; tn++) {
                const int cN = n0 + wn * 64 + tn * 8 + tig * 2;
                float* a = acc[tm][tn];
                float e0 = __expf(a[0] * alpha), e1 = __expf(a[1] * alpha);
                float e2 = __expf(a[2] * alpha), e3 = __expf(a[3] * alpha);
                *(uint32_t*)(Ch + (size_t)z * sC + (size_t)r0 * ldc + cN) = pack_h(e0, e1);
                *(uint32_t*)(Ch + (size_t)z * sC + (size_t)(r0 + 8) * ldc + cN) = pack_h(e2, e3);
                sum0 += e0 + e1;
                sum1 += e2 + e3;
            }
            sum0 += __shfl_xor_sync(~0u, sum0, 1);
            sum0 += __shfl_xor_sync(~0u, sum0, 2);
            sum1 += __shfl_xor_sync(~0u, sum1, 1);
            sum1 += __shfl_xor_sync(~0u, sum1, 2);
            if (tig == 0) {
                rsum[wn * 128 + rr] = sum0;
                rsum[wn * 128 + rr + 8] = sum1;
            }
        }
        __syncthreads();
        if (t < 128) {
            float v = rsum[t] + rsum[128 + t];
            aux[((size_t)z * LQ + m0 + t) * 16 + blockIdx.x] = v;
        }
    } else {
        // OUTMODE 3: fp16 C + per-channel BN partials (sum, sumsq); NT==128 only
        float* bns = (float*)smem;          // [2][128]
        float* bnq = (float*)smem + 256;    // [2][128]
        __syncthreads();
#pragma unroll
        for (int tn = 0; tn < 8; tn++) {
            float cs0 = 0.f, cs1 = 0.f, cq0 = 0.f, cq1 = 0.f;
            const int cN = n0 + wn * 64 + tn * 8 + tig * 2;
#pragma unroll
            for (int tm = 0; tm < 4; tm++) {
                const int r0 = m0 + wm * 64 + tm * 16 + gid;
                float* a = acc[tm][tn];
                float v0 = a[0] * alpha, v1 = a[1] * alpha;
                float v2 = a[2] * alpha, v3 = a[3] * alpha;
                *(uint32_t*)(Ch + (size_t)z * sC + (size_t)r0 * ldc + cN) = pack_h(v0, v1);
                *(uint32_t*)(Ch + (size_t)z * sC + (size_t)(r0 + 8) * ldc + cN) = pack_h(v2, v3);
                cs0 += v0 + v2; cs1 += v1 + v3;
                cq0 += v0 * v0 + v2 * v2; cq1 += v1 * v1 + v3 * v3;
            }
#pragma unroll
            for (int o = 4; o <= 16; o <<= 1) {   // reduce over gid
                cs0 += __shfl_xor_sync(~0u, cs0, o);
                cs1 += __shfl_xor_sync(~0u, cs1, o);
                cq0 += __shfl_xor_sync(~0u, cq0, o);
                cq1 += __shfl_xor_sync(~0u, cq1, o);
            }
            if (gid == 0) {
                const int cl = wn * 64 + tn * 8 + tig * 2;
                bns[wm * 128 + cl] = cs0; bns[wm * 128 + cl + 1] = cs1;
                bnq[wm * 128 + cl] = cq0; bnq[wm * 128 + cl + 1] = cq1;
            }
        }
        __syncthreads();
        if (t < 128) {
            float* pb = aux + (size_t)z * 2 * 128 * DD;
            pb[(size_t)blockIdx.y * DD + n0 + t] = bns[t] + bns[128 + t];
            pb[(size_t)128 * DD + (size_t)blockIdx.y * DD + n0 + t] = bnq[t] + bnq[128 + t];
        }
    }
}

// Finalize: inv[z][i] = 1 / sum of 16 partials. grid = ZB*LQ/256.
__global__ void rowsum_fin(const float* __restrict__ part, float* __restrict__ inv)
{
    const size_t i = (size_t)blockIdx.x * 256 + threadIdx.x;
    const float* p = part + i * 16;
    float s = 0.f;
#pragma unroll
    for (int k = 0; k < 16; k++) s += p[k];
    inv[i] = 1.f / s;
}

// ---------------------------------------------------------------------------
// Prep kernels
// ---------------------------------------------------------------------------
__global__ void convert_q(const float* __restrict__ in, f16* __restrict__ q)
{
    const int l = blockIdx.x, b = blockIdx.y, t = threadIdx.x;
    const float* s = in + (size_t)l * (BB * DD) + (size_t)b * DD;
    const size_t o = ((size_t)b * LQ + l) * DD;
#pragma unroll
    for (int j = 0; j < 3; j++)
        q[o + t + j * 256] = __float2half(s[t + j * 256]);
}

__global__ void convert_w(const float* __restrict__ wa, const float* __restrict__ wv,
                          f16* __restrict__ w)
{
    const int br = blockIdx.y;
    const int i = blockIdx.x * 256 + threadIdx.x;
    w[br * DD * DD + i] = __float2half((br ? wv : wa)[i]);
}

__global__ void prep_kv(const float* __restrict__ xa, const float* __restrict__ xv,
                        f16* __restrict__ kv, f16* __restrict__ kT)
{
    __shared__ uint16_t th[32][33];
    const int z = blockIdx.z, b = z & 7;
    const float* src = (z >> 3) ? xv : xa;
    const int d0 = blockIdx.x * 32, l0 = blockIdx.y * 32;
    const int tx = threadIdx.x, ty = threadIdx.y;
#pragma unroll
    for (int r = 0; r < 4; r++) {
        int l = l0 + ty + r * 8;
        float v = src[(size_t)l * (BB * DD) + (size_t)b * DD + d0 + tx];
        uint16_t h = __half_as_ushort(__float2half(v));
        kv[((size_t)z * LQ + l) * DD + d0 + tx] = __ushort_as_half(h);
        th[ty + r * 8][tx] = h;
    }
    __syncthreads();
#pragma unroll
    for (int r = 0; r < 4; r++) {
        int d = d0 + ty + r * 8;
        kT[((size_t)z * DD + d) * LQ + l0 + tx] = __ushort_as_half(th[tx][ty + r * 8]);
    }
}

// ---------------------------------------------------------------------------
// BN finalize: per-channel scale/shift from partials. grid = (3, 2).
// ---------------------------------------------------------------------------
__global__ void bn_finalize(const float* __restrict__ partAll,
                            const float* __restrict__ ga, const float* __restrict__ ba,
                            const float* __restrict__ gv, const float* __restrict__ bv,
                            float* __restrict__ statsAll)
{
    const int br = blockIdx.y;
    const int c = blockIdx.x * 256 + threadIdx.x;
    const float* part = partAll + (size_t)br * 2 * 128 * DD;
    const float* gamma = br ? gv : ga;
    const float* beta  = br ? bv : ba;
    float* statsOut = statsAll + br * 2 * DD;
    float s = 0.f, q = 0.f;
    for (int k = 0; k < 128; k++) {
        s += part[k * DD + c];
        q += part[128 * DD + k * DD + c];
    }
    const float mean = s * (1.f / (float)MROWS);
    const float var  = q * (1.f / (float)MROWS) - mean * mean;
    const float scale = gamma[c] * rsqrtf(var + 1e-5f);
    statsOut[c]      = scale;
    statsOut[DD + c] = beta[c] - mean * scale;
}

// ---------------------------------------------------------------------------
// Combine: BN-apply + PReLU + residual + LayerNorm. grid = MROWS.
// ---------------------------------------------------------------------------
__global__ void combine_ln(const float* __restrict__ x,
                           const f16* __restrict__ yAll,
                           const float* __restrict__ stats,
                           const float* __restrict__ pa,
                           const float* __restrict__ pv,
                           const float* __restrict__ lng,
                           const float* __restrict__ lnb,
                           float* __restrict__ out)
{
    __shared__ float rs[8], rq[8];
    const int pos = blockIdx.x;
    const int b = pos >> 11, l = pos & 2047;
    const size_t yoff = (size_t)pos * DD;
    const size_t xoff = (size_t)l * (BB * DD) + (size_t)b * DD;
    const int t = threadIdx.x;
    const float aa = pa[0], av = pv[0];
    const f16* ya = yAll;
    const f16* yv = yAll + (size_t)MROWS * DD;

    float vv[3];
    float s = 0.f, q = 0.f;
#pragma unroll
    for (int j = 0; j < 3; j++) {
        const int d = t + j * 256;
        float va = __half2float(ya[yoff + d]) * stats[d] + stats[DD + d];
        va = va > 0.f ? va : aa * va;
        float vb = __half2float(yv[yoff + d]) * stats[2 * DD + d] + stats[3 * DD + d];
        vb = vb > 0.f ? vb : av * vb;
        float val = x[xoff + d] + va + vb;
        vv[j] = val; s += val; q += val * val;
    }
#pragma unroll
    for (int o = 16; o; o >>= 1) {
        s += __shfl_xor_sync(~0u, s, o);
        q += __shfl_xor_sync(~0u, q, o);
    }
    if ((t & 31) == 0) { rs[t >> 5] = s; rq[t >> 5] = q; }
    __syncthreads();
    s = 0.f; q = 0.f;
#pragma unroll
    for (int w = 0; w < 8; w++) { s += rs[w]; q += rq[w]; }
    const float mean = s * (1.f / (float)DD);
    const float var  = q * (1.f / (float)DD) - mean * mean;
    const float rstd = rsqrtf(var + 1e-5f);
#pragma unroll
    for (int j = 0; j < 3; j++) {
        const int d = t + j * 256;
        out[xoff + d] = (vv[j] - mean) * rstd * lng[d] + lnb[d];
    }
}

// ---------------------------------------------------------------------------
// Host orchestration (graph-capturable)
// ---------------------------------------------------------------------------
extern "C" void kernel_launch(void* const* d_in, const int* in_sizes, int n_in,
                              void* d_out, int out_size)
{
    const float* x_a    = (const float*)d_in[0];
    const float* x_v    = (const float*)d_in[1];
    const float* x      = (const float*)d_in[2];
    const float* W_a    = (const float*)d_in[3];
    const float* bn_a_g = (const float*)d_in[5];
    const float* bn_a_b = (const float*)d_in[6];
    const float* pre_a  = (const float*)d_in[7];
    const float* W_v    = (const float*)d_in[8];
    const float* bn_v_g = (const float*)d_in[10];
    const float* bn_v_b = (const float*)d_in[11];
    const float* pre_v  = (const float*)d_in[12];
    const float* ln_g   = (const float*)d_in[13];
    const float* ln_b   = (const float*)d_in[14];
    float* out = (float*)d_out;

    float *part, *stats, *rspart, *rsinv;
    f16 *S, *q, *kv, *kT, *c, *W, *y;
    cudaGetSymbolAddress((void**)&S,      g_S);
    cudaGetSymbolAddress((void**)&q,      g_q);
    cudaGetSymbolAddress((void**)&kv,     g_kv);
    cudaGetSymbolAddress((void**)&kT,     g_kT);
    cudaGetSymbolAddress((void**)&c,      g_c);
    cudaGetSymbolAddress((void**)&W,      g_W);
    cudaGetSymbolAddress((void**)&y,      g_y);
    cudaGetSymbolAddress((void**)&rspart, g_rspart);
    cudaGetSymbolAddress((void**)&rsinv,  g_rsinv);
    cudaGetSymbolAddress((void**)&part,   g_part);
    cudaGetSymbolAddress((void**)&stats,  g_stats);

    const int SMEM_N = 3 * (16384 + 128 * 128);   // 96 KB (narrow)
    const int SMEM_W = 3 * (16384 + 256 * 128);   // 144 KB (wide)
    cudaFuncSetAttribute(mma_gemm<2, 128>, cudaFuncAttributeMaxDynamicSharedMemorySize, SMEM_N);
    cudaFuncSetAttribute(mma_gemm<1, 256>, cudaFuncAttributeMaxDynamicSharedMemorySize, SMEM_W);
    cudaFuncSetAttribute(mma_gemm<3, 128>, cudaFuncAttributeMaxDynamicSharedMemorySize, SMEM_N);

    // Prep: q, W, kv/kvT (both branches)
    convert_q<<<dim3(LQ, BB), 256>>>(x, q);
    convert_w<<<dim3((DD * DD) / 256, 2), 256>>>(W_a, W_v, W);
    prep_kv<<<dim3(DD / 32, LQ / 32, ZB), dim3(32, 8)>>>(x_a, x_v, kv, kT);

    // GEMM1 + exp epilogue: S = exp(scale * q.kv), partial row sums
    mma_gemm<2, 128><<<dim3(16, 16, ZB), 128, SMEM_N>>>(
        q, kv, S, nullptr, rspart,
        DD, LQ, (long)LQ * DD, (long)LQ * DD, (long)LQ * LQ, QKSCALE, 7);

    rowsum_fin<<<(ZB * LQ) / 256, 256>>>(rspart, rsinv);

    // GEMM2 (wide tiles: halves S re-reads): ctx = invsum * (S . kvT)
    mma_gemm<1, 256><<<dim3(3, 16, ZB), 256, SMEM_W>>>(
        S, kT, c, rsinv, nullptr,
        LQ, DD, (long)LQ * LQ, (long)DD * LQ, (long)LQ * DD, 1.f, 0xFF);

    // GEMM3 + fused BN partials: y = ctx . W, partials into g_part
    mma_gemm<3, 128><<<dim3(6, 128, 2), 128, SMEM_N>>>(
        c, W, y, nullptr, part,
        DD, DD, (long)MROWS * DD, (long)DD * DD, (long)MROWS * DD, 1.f, 0xFF);

    bn_finalize<<<dim3(3, 2), 256>>>(part, bn_a_g, bn_a_b, bn_v_g, bn_v_b, stats);

    combine_ln<<<MROWS, 256>>>(x, y, stats, pre_a, pre_v, ln_g, ln_b, out);
}

// round 16
// speedup vs baseline: 1.0575x; 1.0575x over previous
#include <cuda_runtime.h>
#include <cuda_fp16.h>
#include <cstdint>

#define LQ 2048
#define BB 8
#define DD 768
#define MROWS (BB * LQ)
#define ZB (2 * BB)                 // branch*8 + batch
#define QKSCALE 0.0360843918243516f

using f16 = __half;

// ---------------------------------------------------------------------------
// Scratch (device globals; allocation-free per harness rules)
// ---------------------------------------------------------------------------
__device__ __align__(16) f16   g_S[(size_t)ZB * LQ * LQ];     // 128MB exp-logits (unnormalized)
__device__ __align__(16) f16   g_q[(size_t)MROWS * DD];
__device__ __align__(16) f16   g_kv[(size_t)2 * MROWS * DD];
__device__ __align__(16) f16   g_kT[(size_t)2 * MROWS * DD];
__device__ __align__(16) f16   g_c[(size_t)2 * MROWS * DD];
__device__ __align__(16) f16   g_W[2 * DD * DD];
__device__ __align__(16) f16   g_y[(size_t)2 * MROWS * DD];   // conv out fp16, both branches
__device__ float g_rspart[(size_t)ZB * LQ * 16];              // softmax row partial sums
__device__ float g_rsinv[(size_t)ZB * LQ];                    // 1/rowsum
__device__ float g_part[2 * 2 * 128 * DD];                    // BN partials [br][sum|sq][128][768]
__device__ float g_stats[2 * 2 * DD];

// ---------------------------------------------------------------------------
// Helpers (baseline PTX only: ldmatrix / mma.sync / cp.async)
// ---------------------------------------------------------------------------
__device__ __forceinline__ uint32_t smem_u32(const void* p) {
    uint32_t a;
    asm("{ .reg .u64 t; cvta.to.shared.u64 t, %1; cvt.u32.u64 %0, t; }" : "=r"(a) : "l"(p));
    return a;
}
__device__ __forceinline__ void cp16(uint32_t saddr, const void* gaddr) {
    asm volatile("cp.async.cg.shared.global [%0], [%1], 16;" :: "r"(saddr), "l"(gaddr));
}
#define CP_COMMIT() asm volatile("cp.async.commit_group;" ::: "memory")
#define CP_WAIT0()  asm volatile("cp.async.wait_group 0;" ::: "memory")
#define CP_WAIT1()  asm volatile("cp.async.wait_group 1;" ::: "memory")

__device__ __forceinline__ void ldmat_x4(uint32_t& r0, uint32_t& r1, uint32_t& r2,
                                         uint32_t& r3, uint32_t addr) {
    asm volatile("ldmatrix.sync.aligned.m8n8.x4.shared.b16 {%0,%1,%2,%3}, [%4];"
                 : "=r"(r0), "=r"(r1), "=r"(r2), "=r"(r3) : "r"(addr));
}
__device__ __forceinline__ void mma16816(float* c, uint32_t a0, uint32_t a1,
                                         uint32_t a2, uint32_t a3,
                                         uint32_t b0, uint32_t b1) {
    asm volatile(
        "mma.sync.aligned.m16n8k16.row.col.f32.f16.f16.f32 "
        "{%0,%1,%2,%3}, {%4,%5,%6,%7}, {%8,%9}, {%0,%1,%2,%3};"
        : "+f"(c[0]), "+f"(c[1]), "+f"(c[2]), "+f"(c[3])
        : "r"(a0), "r"(a1), "r"(a2), "r"(a3), "r"(b0), "r"(b1));
}

__device__ __forceinline__ uint32_t sw_off(int row, int kbyte) {
    uint32_t off = (uint32_t)row * 128u + (uint32_t)kbyte;
    return off ^ ((off >> 3) & 0x70u);
}
__device__ __forceinline__ uint32_t pack_h(float a, float b) {
    __half2 h = __float22half2_rn(make_float2(a, b));
    return *(uint32_t*)&h;
}

// ---------------------------------------------------------------------------
// fp16 warp-MMA GEMM: C[m,n] = alpha * sum_k A[m,k]*B[n,k]
// 128x128 CTA tile, 128 threads / 4 warps (2x2 grid, 64x64 warp tiles),
// K in 64-chunks, 3-stage cp.async pipeline (32KB/stage), 2 CTAs per SM.
// A batch index = z & amask; B/C batch index = z.
// OUTMODE 1: fp16 C (alpha; optional per-row scale from rowscale[]).
// OUTMODE 2: fp16 exp(alpha*acc) into Ch + per-row partial sums to aux.
// OUTMODE 3: fp16 C + deterministic per-channel BN partials into aux.
// ---------------------------------------------------------------------------
#define STAGE_BYTES 32768
#define B_SM_OFF 16384
#define GEMM_SMEM (3 * STAGE_BYTES)
#define GTHREADS 128

__device__ __forceinline__ void stage_load(uint32_t sdst, const f16* __restrict__ A,
                                           const f16* __restrict__ B,
                                           int K, int k0, int t) {
#pragma unroll
    for (int i = 0; i < 8; i++) {         // A: 128 rows x 8 chunks
        int idx = t + i * GTHREADS;
        int row = idx >> 3, ch = idx & 7;
        cp16(sdst + sw_off(row, ch * 16), A + (size_t)row * K + k0 + ch * 8);
    }
#pragma unroll
    for (int i = 0; i < 8; i++) {         // B: 128 rows x 8 chunks
        int idx = t + i * GTHREADS;
        int row = idx >> 3, ch = idx & 7;
        cp16(sdst + B_SM_OFF + sw_off(row, ch * 16), B + (size_t)row * K + k0 + ch * 8);
    }
}

template<int OUTMODE>
__global__ void __launch_bounds__(GTHREADS, 2)
mma_gemm(const f16* __restrict__ A, const f16* __restrict__ B,
         f16* __restrict__ Ch, const float* __restrict__ rowscale,
         float* __restrict__ aux,
         int K, int ldc, long sA, long sB, long sC, float alpha, int amask)
{
    extern __shared__ __align__(1024) char smem[];
    const uint32_t sb = smem_u32(smem);
    const int t = threadIdx.x, lane = t & 31, wid = t >> 5;
    const int wm = wid & 1, wn = wid >> 1;          // 2x2 warp grid, 64x64 tiles
    const int m0 = blockIdx.y * 128, n0 = blockIdx.x * 128, z = blockIdx.z;
    const int kiters = K >> 6;

    A += (size_t)(z & amask) * sA + (size_t)m0 * K;
    B += (size_t)z * sB + (size_t)n0 * K;

    float acc[4][8][4];
#pragma unroll
    for (int i = 0; i < 4; i++)
#pragma unroll
        for (int j = 0; j < 8; j++)
#pragma unroll
            for (int q = 0; q < 4; q++) acc[i][j][q] = 0.f;

    // ldmatrix lane-address components
    const int a_m_add = (lane & 7) + ((lane >> 3) & 1) * 8;
    const int a_k_add = ((lane >> 4) & 1) * 8;
    const int b_n_add = (lane & 7) + ((lane >> 4) << 3);
    const int b_k_add = ((lane >> 3) & 1) * 8;

    stage_load(sb, A, B, K, 0, t);
    CP_COMMIT();
    if (kiters > 1) {
        stage_load(sb + STAGE_BYTES, A, B, K, 64, t);
        CP_COMMIT();
    }

    uint32_t cur = 0;
    for (int it = 0; it < kiters; it++) {
        if (it + 1 < kiters) { CP_WAIT1(); } else { CP_WAIT0(); }
        __syncthreads();
        if (it + 2 < kiters) {
            uint32_t nxt = cur + 2; if (nxt >= 3) nxt -= 3;
            stage_load(sb + nxt * STAGE_BYTES, A, B, K, (it + 2) << 6, t);
            CP_COMMIT();
        }
        const uint32_t st = sb + cur * STAGE_BYTES;

#pragma unroll
        for (int ks = 0; ks < 4; ks++) {
            const int kb = ks * 16;
            uint32_t ah[4][4];
#pragma unroll
            for (int tm = 0; tm < 4; tm++) {
                int m = wm * 64 + tm * 16 + a_m_add;
                uint32_t so = sw_off(m, (kb + a_k_add) * 2);
                ldmat_x4(ah[tm][0], ah[tm][1], ah[tm][2], ah[tm][3], st + so);
            }
            uint32_t bh[8][2];
#pragma unroll
            for (int tn2 = 0; tn2 < 4; tn2++) {
                int n = wn * 64 + tn2 * 16 + b_n_add;
                uint32_t so = sw_off(n, (kb + b_k_add) * 2);
                ldmat_x4(bh[tn2 * 2][0], bh[tn2 * 2][1],
                         bh[tn2 * 2 + 1][0], bh[tn2 * 2 + 1][1], st + B_SM_OFF + so);
            }
#pragma unroll
            for (int tm = 0; tm < 4; tm++)
#pragma unroll
                for (int tn = 0; tn < 8; tn++)
                    mma16816(acc[tm][tn], ah[tm][0], ah[tm][1], ah[tm][2], ah[tm][3],
                             bh[tn][0], bh[tn][1]);
        }
        cur = cur + 1; if (cur >= 3) cur -= 3;
    }

    const int gid = lane >> 2, tig = lane & 3;
    if (OUTMODE == 1) {
#pragma unroll
        for (int tm = 0; tm < 4; tm++) {
            const int r0 = m0 + wm * 64 + tm * 16 + gid;
            float rs0 = 1.f, rs1 = 1.f;
            if (rowscale) {
                rs0 = rowscale[(size_t)z * LQ + r0];
                rs1 = rowscale[(size_t)z * LQ + r0 + 8];
            }
#pragma unroll
            for (int tn = 0; tn < 8; tn++) {
                const int cN = n0 + wn * 64 + tn * 8 + tig * 2;
                float* a = acc[tm][tn];
                *(uint32_t*)(Ch + (size_t)z * sC + (size_t)r0 * ldc + cN) =
                    pack_h(a[0] * alpha * rs0, a[1] * alpha * rs0);
                *(uint32_t*)(Ch + (size_t)z * sC + (size_t)(r0 + 8) * ldc + cN) =
                    pack_h(a[2] * alpha * rs1, a[3] * alpha * rs1);
            }
        }
    } else if (OUTMODE == 2) {
        // exp epilogue + deterministic per-row partial sums
        float* rsum = (float*)smem;
        __syncthreads();
#pragma unroll
        for (int tm = 0; tm < 4; tm++) {
            const int rr = wm * 64 + tm * 16 + gid;
            const int r0 = m0 + rr;
            float sum0 = 0.f, sum1 = 0.f;
#pragma unroll
            for (int tn = 0; tn < 8; tn++) {
                const int cN = n0 + wn * 64 + tn * 8 + tig * 2;
                float* a = acc[tm][tn];
                float e0 = __expf(a[0] * alpha), e1 = __expf(a[1] * alpha);
                float e2 = __expf(a[2] * alpha), e3 = __expf(a[3] * alpha);
                *(uint32_t*)(Ch + (size_t)z * sC + (size_t)r0 * ldc + cN) = pack_h(e0, e1);
                *(uint32_t*)(Ch + (size_t)z * sC + (size_t)(r0 + 8) * ldc + cN) = pack_h(e2, e3);
                sum0 += e0 + e1;
                sum1 += e2 + e3;
            }
            sum0 += __shfl_xor_sync(~0u, sum0, 1);
            sum0 += __shfl_xor_sync(~0u, sum0, 2);
            sum1 += __shfl_xor_sync(~0u, sum1, 1);
            sum1 += __shfl_xor_sync(~0u, sum1, 2);
            if (tig == 0) {
                rsum[wn * 128 + rr] = sum0;
                rsum[wn * 128 + rr + 8] = sum1;
            }
        }
        __syncthreads();
        if (t < 128) {
            float v = rsum[t] + rsum[128 + t];
            aux[((size_t)z * LQ + m0 + t) * 16 + blockIdx.x] = v;
        }
    } else {
        // OUTMODE 3: fp16 C + per-channel BN partials (sum, sumsq)
        float* bns = (float*)smem;          // [2][128]
        float* bnq = (float*)smem + 256;    // [2][128]
        __syncthreads();
#pragma unroll
        for (int tn = 0; tn < 8; tn++) {
            float cs0 = 0.f, cs1 = 0.f, cq0 = 0.f, cq1 = 0.f;
            const int cN = n0 + wn * 64 + tn * 8 + tig * 2;
#pragma unroll
            for (int tm = 0; tm < 4; tm++) {
                const int r0 = m0 + wm * 64 + tm * 16 + gid;
                float* a = acc[tm][tn];
                float v0 = a[0] * alpha, v1 = a[1] * alpha;
                float v2 = a[2] * alpha, v3 = a[3] * alpha;
                *(uint32_t*)(Ch + (size_t)z * sC + (size_t)r0 * ldc + cN) = pack_h(v0, v1);
                *(uint32_t*)(Ch + (size_t)z * sC + (size_t)(r0 + 8) * ldc + cN) = pack_h(v2, v3);
                cs0 += v0 + v2; cs1 += v1 + v3;
                cq0 += v0 * v0 + v2 * v2; cq1 += v1 * v1 + v3 * v3;
            }
#pragma unroll
            for (int o = 4; o <= 16; o <<= 1) {   // reduce over gid
                cs0 += __shfl_xor_sync(~0u, cs0, o);
                cs1 += __shfl_xor_sync(~0u, cs1, o);
                cq0 += __shfl_xor_sync(~0u, cq0, o);
                cq1 += __shfl_xor_sync(~0u, cq1, o);
            }
            if (gid == 0) {
                const int cl = wn * 64 + tn * 8 + tig * 2;
                bns[wm * 128 + cl] = cs0; bns[wm * 128 + cl + 1] = cs1;
                bnq[wm * 128 + cl] = cq0; bnq[wm * 128 + cl + 1] = cq1;
            }
        }
        __syncthreads();
        if (t < 128) {
            float* pb = aux + (size_t)z * 2 * 128 * DD;
            pb[(size_t)blockIdx.y * DD + n0 + t] = bns[t] + bns[128 + t];
            pb[(size_t)128 * DD + (size_t)blockIdx.y * DD + n0 + t] = bnq[t] + bnq[128 + t];
        }
    }
}

// Finalize: inv[z][i] = 1 / sum of 16 partials. grid = ZB*LQ/256.
__global__ void rowsum_fin(const float* __restrict__ part, float* __restrict__ inv)
{
    const size_t i = (size_t)blockIdx.x * 256 + threadIdx.x;
    const float* p = part + i * 16;
    float s = 0.f;
#pragma unroll
    for (int k = 0; k < 16; k++) s += p[k];
    inv[i] = 1.f / s;
}

// ---------------------------------------------------------------------------
// Prep kernels
// ---------------------------------------------------------------------------
__global__ void convert_q(const float* __restrict__ in, f16* __restrict__ q)
{
    const int l = blockIdx.x, b = blockIdx.y, t = threadIdx.x;
    const float* s = in + (size_t)l * (BB * DD) + (size_t)b * DD;
    const size_t o = ((size_t)b * LQ + l) * DD;
#pragma unroll
    for (int j = 0; j < 3; j++)
        q[o + t + j * 256] = __float2half(s[t + j * 256]);
}

__global__ void convert_w(const float* __restrict__ wa, const float* __restrict__ wv,
                          f16* __restrict__ w)
{
    const int br = blockIdx.y;
    const int i = blockIdx.x * 256 + threadIdx.x;
    w[br * DD * DD + i] = __float2half((br ? wv : wa)[i]);
}

__global__ void prep_kv(const float* __restrict__ xa, const float* __restrict__ xv,
                        f16* __restrict__ kv, f16* __restrict__ kT)
{
    __shared__ uint16_t th[32][33];
    const int z = blockIdx.z, b = z & 7;
    const float* src = (z >> 3) ? xv : xa;
    const int d0 = blockIdx.x * 32, l0 = blockIdx.y * 32;
    const int tx = threadIdx.x, ty = threadIdx.y;
#pragma unroll
    for (int r = 0; r < 4; r++) {
        int l = l0 + ty + r * 8;
        float v = src[(size_t)l * (BB * DD) + (size_t)b * DD + d0 + tx];
        uint16_t h = __half_as_ushort(__float2half(v));
        kv[((size_t)z * LQ + l) * DD + d0 + tx] = __ushort_as_half(h);
        th[ty + r * 8][tx] = h;
    }
    __syncthreads();
#pragma unroll
    for (int r = 0; r < 4; r++) {
        int d = d0 + ty + r * 8;
        kT[((size_t)z * DD + d) * LQ + l0 + tx] = __ushort_as_half(th[tx][ty + r * 8]);
    }
}

// ---------------------------------------------------------------------------
// BN finalize: per-channel scale/shift from partials. grid = (3, 2).
// ---------------------------------------------------------------------------
__global__ void bn_finalize(const float* __restrict__ partAll,
                            const float* __restrict__ ga, const float* __restrict__ ba,
                            const float* __restrict__ gv, const float* __restrict__ bv,
                            float* __restrict__ statsAll)
{
    const int br = blockIdx.y;
    const int c = blockIdx.x * 256 + threadIdx.x;
    const float* part = partAll + (size_t)br * 2 * 128 * DD;
    const float* gamma = br ? gv : ga;
    const float* beta  = br ? bv : ba;
    float* statsOut = statsAll + br * 2 * DD;
    float s = 0.f, q = 0.f;
    for (int k = 0; k < 128; k++) {
        s += part[k * DD + c];
        q += part[128 * DD + k * DD + c];
    }
    const float mean = s * (1.f / (float)MROWS);
    const float var  = q * (1.f / (float)MROWS) - mean * mean;
    const float scale = gamma[c] * rsqrtf(var + 1e-5f);
    statsOut[c]      = scale;
    statsOut[DD + c] = beta[c] - mean * scale;
}

// ---------------------------------------------------------------------------
// Combine: BN-apply + PReLU + residual + LayerNorm. grid = MROWS.
// ---------------------------------------------------------------------------
__global__ void combine_ln(const float* __restrict__ x,
                           const f16* __restrict__ yAll,
                           const float* __restrict__ stats,
                           const float* __restrict__ pa,
                           const float* __restrict__ pv,
                           const float* __restrict__ lng,
                           const float* __restrict__ lnb,
                           float* __restrict__ out)
{
    __shared__ float rs[8], rq[8];
    const int pos = blockIdx.x;
    const int b = pos >> 11, l = pos & 2047;
    const size_t yoff = (size_t)pos * DD;
    const size_t xoff = (size_t)l * (BB * DD) + (size_t)b * DD;
    const int t = threadIdx.x;
    const float aa = pa[0], av = pv[0];
    const f16* ya = yAll;
    const f16* yv = yAll + (size_t)MROWS * DD;

    float vv[3];
    float s = 0.f, q = 0.f;
#pragma unroll
    for (int j = 0; j < 3; j++) {
        const int d = t + j * 256;
        float va = __half2float(ya[yoff + d]) * stats[d] + stats[DD + d];
        va = va > 0.f ? va : aa * va;
        float vb = __half2float(yv[yoff + d]) * stats[2 * DD + d] + stats[3 * DD + d];
        vb = vb > 0.f ? vb : av * vb;
        float val = x[xoff + d] + va + vb;
        vv[j] = val; s += val; q += val * val;
    }
#pragma unroll
    for (int o = 16; o; o >>= 1) {
        s += __shfl_xor_sync(~0u, s, o);
        q += __shfl_xor_sync(~0u, q, o);
    }
    if ((t & 31) == 0) { rs[t >> 5] = s; rq[t >> 5] = q; }
    __syncthreads();
    s = 0.f; q = 0.f;
#pragma unroll
    for (int w = 0; w < 8; w++) { s += rs[w]; q += rq[w]; }
    const float mean = s * (1.f / (float)DD);
    const float var  = q * (1.f / (float)DD) - mean * mean;
    const float rstd = rsqrtf(var + 1e-5f);
#pragma unroll
    for (int j = 0; j < 3; j++) {
        const int d = t + j * 256;
        out[xoff + d] = (vv[j] - mean) * rstd * lng[d] + lnb[d];
    }
}

// ---------------------------------------------------------------------------
// Host orchestration (graph-capturable)
// ---------------------------------------------------------------------------
extern "C" void kernel_launch(void* const* d_in, const int* in_sizes, int n_in,
                              void* d_out, int out_size)
{
    const float* x_a    = (const float*)d_in[0];
    const float* x_v    = (const float*)d_in[1];
    const float* x      = (const float*)d_in[2];
    const float* W_a    = (const float*)d_in[3];
    const float* bn_a_g = (const float*)d_in[5];
    const float* bn_a_b = (const float*)d_in[6];
    const float* pre_a  = (const float*)d_in[7];
    const float* W_v    = (const float*)d_in[8];
    const float* bn_v_g = (const float*)d_in[10];
    const float* bn_v_b = (const float*)d_in[11];
    const float* pre_v  = (const float*)d_in[12];
    const float* ln_g   = (const float*)d_in[13];
    const float* ln_b   = (const float*)d_in[14];
    float* out = (float*)d_out;

    float *part, *stats, *rspart, *rsinv;
    f16 *S, *q, *kv, *kT, *c, *W, *y;
    cudaGetSymbolAddress((void**)&S,      g_S);
    cudaGetSymbolAddress((void**)&q,      g_q);
    cudaGetSymbolAddress((void**)&kv,     g_kv);
    cudaGetSymbolAddress((void**)&kT,     g_kT);
    cudaGetSymbolAddress((void**)&c,      g_c);
    cudaGetSymbolAddress((void**)&W,      g_W);
    cudaGetSymbolAddress((void**)&y,      g_y);
    cudaGetSymbolAddress((void**)&rspart, g_rspart);
    cudaGetSymbolAddress((void**)&rsinv,  g_rsinv);
    cudaGetSymbolAddress((void**)&part,   g_part);
    cudaGetSymbolAddress((void**)&stats,  g_stats);

    cudaFuncSetAttribute(mma_gemm<1>, cudaFuncAttributeMaxDynamicSharedMemorySize, GEMM_SMEM);
    cudaFuncSetAttribute(mma_gemm<2>, cudaFuncAttributeMaxDynamicSharedMemorySize, GEMM_SMEM);
    cudaFuncSetAttribute(mma_gemm<3>, cudaFuncAttributeMaxDynamicSharedMemorySize, GEMM_SMEM);

    // Prep: q, W, kv/kvT (both branches)
    convert_q<<<dim3(LQ, BB), 256>>>(x, q);
    convert_w<<<dim3((DD * DD) / 256, 2), 256>>>(W_a, W_v, W);
    prep_kv<<<dim3(DD / 32, LQ / 32, ZB), dim3(32, 8)>>>(x_a, x_v, kv, kT);

    // GEMM1 + exp epilogue: S = exp(scale * q.kv), partial row sums
    mma_gemm<2><<<dim3(16, 16, ZB), GTHREADS, GEMM_SMEM>>>(
        q, kv, S, nullptr, rspart,
        DD, LQ, (long)LQ * DD, (long)LQ * DD, (long)LQ * LQ, QKSCALE, 7);

    rowsum_fin<<<(ZB * LQ) / 256, 256>>>(rspart, rsinv);

    // GEMM2 (narrow, 2 CTAs/SM): ctx = invsum * (S . kvT)
    mma_gemm<1><<<dim3(6, 16, ZB), GTHREADS, GEMM_SMEM>>>(
        S, kT, c, rsinv, nullptr,
        LQ, DD, (long)LQ * LQ, (long)DD * LQ, (long)LQ * DD, 1.f, 0xFF);

    // GEMM3 + fused BN partials: y = ctx . W, partials into g_part
    mma_gemm<3><<<dim3(6, 128, 2), GTHREADS, GEMM_SMEM>>>(
        c, W, y, nullptr, part,
        DD, DD, (long)MROWS * DD, (long)DD * DD, (long)MROWS * DD, 1.f, 0xFF);

    bn_finalize<<<dim3(3, 2), 256>>>(part, bn_a_g, bn_a_b, bn_v_g, bn_v_b, stats);

    combine_ln<<<MROWS, 256>>>(x, y, stats, pre_a, pre_v, ln_g, ln_b, out);
}

// round 17
// speedup vs baseline: 1.0585x; 1.0009x over previous
#include <cuda_runtime.h>
#include <cuda_fp16.h>
#include <cstdint>

#define LQ 2048
#define BB 8
#define DD 768
#define MROWS (BB * LQ)
#define ZB (2 * BB)                 // branch*8 + batch
#define QKSCALE 0.0360843918243516f

using f16 = __half;

// ---------------------------------------------------------------------------
// Scratch (device globals; allocation-free per harness rules)
// ---------------------------------------------------------------------------
__device__ __align__(16) f16   g_S[(size_t)ZB * LQ * LQ];     // 128MB exp-logits (unnormalized)
__device__ __align__(16) f16   g_q[(size_t)MROWS * DD];
__device__ __align__(16) f16   g_kv[(size_t)2 * MROWS * DD];
__device__ __align__(16) f16   g_kT[(size_t)2 * MROWS * DD];
__device__ __align__(16) f16   g_c[(size_t)2 * MROWS * DD];
__device__ __align__(16) f16   g_W[2 * DD * DD];
__device__ __align__(16) f16   g_y[(size_t)2 * MROWS * DD];   // conv out fp16, both branches
__device__ float g_rspart[(size_t)ZB * LQ * 16];              // softmax row partial sums
__device__ float g_part[2 * 2 * 128 * DD];                    // BN partials [br][sum|sq][128][768]
__device__ float g_stats[2 * 2 * DD];

// ---------------------------------------------------------------------------
// Helpers (baseline PTX only: ldmatrix / mma.sync / cp.async)
// ---------------------------------------------------------------------------
__device__ __forceinline__ uint32_t smem_u32(const void* p) {
    uint32_t a;
    asm("{ .reg .u64 t; cvta.to.shared.u64 t, %1; cvt.u32.u64 %0, t; }" : "=r"(a) : "l"(p));
    return a;
}
__device__ __forceinline__ void cp16(uint32_t saddr, const void* gaddr) {
    asm volatile("cp.async.cg.shared.global [%0], [%1], 16;" :: "r"(saddr), "l"(gaddr));
}
#define CP_COMMIT() asm volatile("cp.async.commit_group;" ::: "memory")
#define CP_WAIT0()  asm volatile("cp.async.wait_group 0;" ::: "memory")
#define CP_WAIT1()  asm volatile("cp.async.wait_group 1;" ::: "memory")

__device__ __forceinline__ void ldmat_x4(uint32_t& r0, uint32_t& r1, uint32_t& r2,
                                         uint32_t& r3, uint32_t addr) {
    asm volatile("ldmatrix.sync.aligned.m8n8.x4.shared.b16 {%0,%1,%2,%3}, [%4];"
                 : "=r"(r0), "=r"(r1), "=r"(r2), "=r"(r3) : "r"(addr));
}
__device__ __forceinline__ void mma16816(float* c, uint32_t a0, uint32_t a1,
                                         uint32_t a2, uint32_t a3,
                                         uint32_t b0, uint32_t b1) {
    asm volatile(
        "mma.sync.aligned.m16n8k16.row.col.f32.f16.f16.f32 "
        "{%0,%1,%2,%3}, {%4,%5,%6,%7}, {%8,%9}, {%0,%1,%2,%3};"
        : "+f"(c[0]), "+f"(c[1]), "+f"(c[2]), "+f"(c[3])
        : "r"(a0), "r"(a1), "r"(a2), "r"(a3), "r"(b0), "r"(b1));
}

__device__ __forceinline__ uint32_t sw_off(int row, int kbyte) {
    uint32_t off = (uint32_t)row * 128u + (uint32_t)kbyte;
    return off ^ ((off >> 3) & 0x70u);
}
__device__ __forceinline__ uint32_t pack_h(float a, float b) {
    __half2 h = __float22half2_rn(make_float2(a, b));
    return *(uint32_t*)&h;
}

// ---------------------------------------------------------------------------
// fp16 warp-MMA GEMM: C[m,n] = alpha * sum_k A[m,k]*B[n,k]
// 128x128 CTA tile, 128 threads / 4 warps (2x2 grid, 64x64 warp tiles),
// K in 64-chunks, 3-stage cp.async pipeline (32KB/stage), 2 CTAs per SM.
// A batch index = z & amask; B/C batch index = z.
// OUTMODE 1: fp16 C (alpha; optional per-row scale: rsp = rowsum partials,
//            inv computed in prologue into smem, applied in epilogue).
// OUTMODE 2: fp16 exp(alpha*acc) into Ch + per-row partial sums to aux.
// OUTMODE 3: fp16 C + deterministic per-channel BN partials into aux.
// ---------------------------------------------------------------------------
#define STAGE_BYTES 32768
#define B_SM_OFF 16384
#define GEMM_SMEM (3 * STAGE_BYTES + 512)
#define RS_SM_OFF (3 * STAGE_BYTES)
#define GTHREADS 128

__device__ __forceinline__ void stage_load(uint32_t sdst, const f16* __restrict__ A,
                                           const f16* __restrict__ B,
                                           int K, int k0, int t) {
#pragma unroll
    for (int i = 0; i < 8; i++) {         // A: 128 rows x 8 chunks
        int idx = t + i * GTHREADS;
        int row = idx >> 3, ch = idx & 7;
        cp16(sdst + sw_off(row, ch * 16), A + (size_t)row * K + k0 + ch * 8);
    }
#pragma unroll
    for (int i = 0; i < 8; i++) {         // B: 128 rows x 8 chunks
        int idx = t + i * GTHREADS;
        int row = idx >> 3, ch = idx & 7;
        cp16(sdst + B_SM_OFF + sw_off(row, ch * 16), B + (size_t)row * K + k0 + ch * 8);
    }
}

template<int OUTMODE>
__global__ void __launch_bounds__(GTHREADS, 2)
mma_gemm(const f16* __restrict__ A, const f16* __restrict__ B,
         f16* __restrict__ Ch, const float* __restrict__ rsp,
         float* __restrict__ aux,
         int K, int ldc, long sA, long sB, long sC, float alpha, int amask)
{
    extern __shared__ __align__(1024) char smem[];
    const uint32_t sb = smem_u32(smem);
    const int t = threadIdx.x, lane = t & 31, wid = t >> 5;
    const int wm = wid & 1, wn = wid >> 1;          // 2x2 warp grid, 64x64 tiles
    const int m0 = blockIdx.y * 128, n0 = blockIdx.x * 128, z = blockIdx.z;
    const int kiters = K >> 6;

    A += (size_t)(z & amask) * sA + (size_t)m0 * K;
    B += (size_t)z * sB + (size_t)n0 * K;

    float acc[4][8][4];
#pragma unroll
    for (int i = 0; i < 4; i++)
#pragma unroll
        for (int j = 0; j < 8; j++)
#pragma unroll
            for (int q = 0; q < 4; q++) acc[i][j][q] = 0.f;

    // ldmatrix lane-address components
    const int a_m_add = (lane & 7) + ((lane >> 3) & 1) * 8;
    const int a_k_add = ((lane >> 4) & 1) * 8;
    const int b_n_add = (lane & 7) + ((lane >> 4) << 3);
    const int b_k_add = ((lane >> 3) & 1) * 8;

    stage_load(sb, A, B, K, 0, t);
    CP_COMMIT();

    // OUTMODE 1 prologue: per-row 1/rowsum into smem (overlaps stage-0 loads;
    // deterministic fixed-order sum, identical to the old rowsum_fin kernel)
    if (OUTMODE == 1 && rsp) {
        float* rsinv_s = (float*)(smem + RS_SM_OFF);
        if (t < 128) {
            const float* p = rsp + ((size_t)z * LQ + m0 + t) * 16;
            float s = 0.f;
#pragma unroll
            for (int k = 0; k < 16; k++) s += p[k];
            rsinv_s[t] = 1.f / s;
        }
    }

    if (kiters > 1) {
        stage_load(sb + STAGE_BYTES, A, B, K, 64, t);
        CP_COMMIT();
    }

    uint32_t cur = 0;
    for (int it = 0; it < kiters; it++) {
        if (it + 1 < kiters) { CP_WAIT1(); } else { CP_WAIT0(); }
        __syncthreads();
        if (it + 2 < kiters) {
            uint32_t nxt = cur + 2; if (nxt >= 3) nxt -= 3;
            stage_load(sb + nxt * STAGE_BYTES, A, B, K, (it + 2) << 6, t);
            CP_COMMIT();
        }
        const uint32_t st = sb + cur * STAGE_BYTES;

#pragma unroll
        for (int ks = 0; ks < 4; ks++) {
            const int kb = ks * 16;
            uint32_t ah[4][4];
#pragma unroll
            for (int tm = 0; tm < 4; tm++) {
                int m = wm * 64 + tm * 16 + a_m_add;
                uint32_t so = sw_off(m, (kb + a_k_add) * 2);
                ldmat_x4(ah[tm][0], ah[tm][1], ah[tm][2], ah[tm][3], st + so);
            }
            uint32_t bh[8][2];
#pragma unroll
            for (int tn2 = 0; tn2 < 4; tn2++) {
                int n = wn * 64 + tn2 * 16 + b_n_add;
                uint32_t so = sw_off(n, (kb + b_k_add) * 2);
                ldmat_x4(bh[tn2 * 2][0], bh[tn2 * 2][1],
                         bh[tn2 * 2 + 1][0], bh[tn2 * 2 + 1][1], st + B_SM_OFF + so);
            }
#pragma unroll
            for (int tm = 0; tm < 4; tm++)
#pragma unroll
                for (int tn = 0; tn < 8; tn++)
                    mma16816(acc[tm][tn], ah[tm][0], ah[tm][1], ah[tm][2], ah[tm][3],
                             bh[tn][0], bh[tn][1]);
        }
        cur = cur + 1; if (cur >= 3) cur -= 3;
    }

    const int gid = lane >> 2, tig = lane & 3;
    if (OUTMODE == 1) {
        const float* rsinv_s = (const float*)(smem + RS_SM_OFF);
#pragma unroll
        for (int tm = 0; tm < 4; tm++) {
            const int rr = wm * 64 + tm * 16 + gid;
            const int r0 = m0 + rr;
            float rs0 = 1.f, rs1 = 1.f;
            if (rsp) { rs0 = rsinv_s[rr]; rs1 = rsinv_s[rr + 8]; }
#pragma unroll
            for (int tn = 0; tn < 8; tn++) {
                const int cN = n0 + wn * 64 + tn * 8 + tig * 2;
                float* a = acc[tm][tn];
                *(uint32_t*)(Ch + (size_t)z * sC + (size_t)r0 * ldc + cN) =
                    pack_h(a[0] * alpha * rs0, a[1] * alpha * rs0);
                *(uint32_t*)(Ch + (size_t)z * sC + (size_t)(r0 + 8) * ldc + cN) =
                    pack_h(a[2] * alpha * rs1, a[3] * alpha * rs1);
            }
        }
    } else if (OUTMODE == 2) {
        // exp epilogue + deterministic per-row partial sums
        float* rsum = (float*)smem;
        __syncthreads();
#pragma unroll
        for (int tm = 0; tm < 4; tm++) {
            const int rr = wm * 64 + tm * 16 + gid;
            const int r0 = m0 + rr;
            float sum0 = 0.f, sum1 = 0.f;
#pragma unroll
            for (int tn = 0; tn < 8; tn++) {
                const int cN = n0 + wn * 64 + tn * 8 + tig * 2;
                float* a = acc[tm][tn];
                float e0 = __expf(a[0] * alpha), e1 = __expf(a[1] * alpha);
                float e2 = __expf(a[2] * alpha), e3 = __expf(a[3] * alpha);
                *(uint32_t*)(Ch + (size_t)z * sC + (size_t)r0 * ldc + cN) = pack_h(e0, e1);
                *(uint32_t*)(Ch + (size_t)z * sC + (size_t)(r0 + 8) * ldc + cN) = pack_h(e2, e3);
                sum0 += e0 + e1;
                sum1 += e2 + e3;
            }
            sum0 += __shfl_xor_sync(~0u, sum0, 1);
            sum0 += __shfl_xor_sync(~0u, sum0, 2);
            sum1 += __shfl_xor_sync(~0u, sum1, 1);
            sum1 += __shfl_xor_sync(~0u, sum1, 2);
            if (tig == 0) {
                rsum[wn * 128 + rr] = sum0;
                rsum[wn * 128 + rr + 8] = sum1;
            }
        }
        __syncthreads();
        if (t < 128) {
            float v = rsum[t] + rsum[128 + t];
            aux[((size_t)z * LQ + m0 + t) * 16 + blockIdx.x] = v;
        }
    } else {
        // OUTMODE 3: fp16 C + per-channel BN partials (sum, sumsq)
        float* bns = (float*)smem;          // [2][128]
        float* bnq = (float*)smem + 256;    // [2][128]
        __syncthreads();
#pragma unroll
        for (int tn = 0; tn < 8; tn++) {
            float cs0 = 0.f, cs1 = 0.f, cq0 = 0.f, cq1 = 0.f;
            const int cN = n0 + wn * 64 + tn * 8 + tig * 2;
#pragma unroll
            for (int tm = 0; tm < 4; tm++) {
                const int r0 = m0 + wm * 64 + tm * 16 + gid;
                float* a = acc[tm][tn];
                float v0 = a[0] * alpha, v1 = a[1] * alpha;
                float v2 = a[2] * alpha, v3 = a[3] * alpha;
                *(uint32_t*)(Ch + (size_t)z * sC + (size_t)r0 * ldc + cN) = pack_h(v0, v1);
                *(uint32_t*)(Ch + (size_t)z * sC + (size_t)(r0 + 8) * ldc + cN) = pack_h(v2, v3);
                cs0 += v0 + v2; cs1 += v1 + v3;
                cq0 += v0 * v0 + v2 * v2; cq1 += v1 * v1 + v3 * v3;
            }
#pragma unroll
            for (int o = 4; o <= 16; o <<= 1) {   // reduce over gid
                cs0 += __shfl_xor_sync(~0u, cs0, o);
                cs1 += __shfl_xor_sync(~0u, cs1, o);
                cq0 += __shfl_xor_sync(~0u, cq0, o);
                cq1 += __shfl_xor_sync(~0u, cq1, o);
            }
            if (gid == 0) {
                const int cl = wn * 64 + tn * 8 + tig * 2;
                bns[wm * 128 + cl] = cs0; bns[wm * 128 + cl + 1] = cs1;
                bnq[wm * 128 + cl] = cq0; bnq[wm * 128 + cl + 1] = cq1;
            }
        }
        __syncthreads();
        if (t < 128) {
            float* pb = aux + (size_t)z * 2 * 128 * DD;
            pb[(size_t)blockIdx.y * DD + n0 + t] = bns[t] + bns[128 + t];
            pb[(size_t)128 * DD + (size_t)blockIdx.y * DD + n0 + t] = bnq[t] + bnq[128 + t];
        }
    }
}

// ---------------------------------------------------------------------------
// Prep: z<16 -> kv/kvT from x_a/x_v; z>=16 -> q from x (b = z-16).
// ---------------------------------------------------------------------------
__global__ void prep_all(const float* __restrict__ xa, const float* __restrict__ xv,
                         const float* __restrict__ x,
                         f16* __restrict__ kv, f16* __restrict__ kT,
                         f16* __restrict__ q)
{
    __shared__ uint16_t th[32][33];
    const int z = blockIdx.z;
    const int d0 = blockIdx.x * 32, l0 = blockIdx.y * 32;
    const int tx = threadIdx.x, ty = threadIdx.y;

    if (z >= ZB) {
        const int b = z - ZB;
#pragma unroll
        for (int r = 0; r < 4; r++) {
            int l = l0 + ty + r * 8;
            float v = x[(size_t)l * (BB * DD) + (size_t)b * DD + d0 + tx];
            q[((size_t)b * LQ + l) * DD + d0 + tx] = __float2half(v);
        }
        return;
    }

    const int b = z & 7;
    const float* src = (z >> 3) ? xv : xa;
#pragma unroll
    for (int r = 0; r < 4; r++) {
        int l = l0 + ty + r * 8;
        float v = src[(size_t)l * (BB * DD) + (size_t)b * DD + d0 + tx];
        uint16_t h = __half_as_ushort(__float2half(v));
        kv[((size_t)z * LQ + l) * DD + d0 + tx] = __ushort_as_half(h);
        th[ty + r * 8][tx] = h;
    }
    __syncthreads();
#pragma unroll
    for (int r = 0; r < 4; r++) {
        int d = d0 + ty + r * 8;
        kT[((size_t)z * DD + d) * LQ + l0 + tx] = __ushort_as_half(th[tx][ty + r * 8]);
    }
}

__global__ void convert_w(const float* __restrict__ wa, const float* __restrict__ wv,
                          f16* __restrict__ w)
{
    const int br = blockIdx.y;
    const int i = blockIdx.x * 256 + threadIdx.x;
    w[br * DD * DD + i] = __float2half((br ? wv : wa)[i]);
}

// ---------------------------------------------------------------------------
// BN finalize: per-channel scale/shift from partials. grid = (3, 2).
// ---------------------------------------------------------------------------
__global__ void bn_finalize(const float* __restrict__ partAll,
                            const float* __restrict__ ga, const float* __restrict__ ba,
                            const float* __restrict__ gv, const float* __restrict__ bv,
                            float* __restrict__ statsAll)
{
    const int br = blockIdx.y;
    const int c = blockIdx.x * 256 + threadIdx.x;
    const float* part = partAll + (size_t)br * 2 * 128 * DD;
    const float* gamma = br ? gv : ga;
    const float* beta  = br ? bv : ba;
    float* statsOut = statsAll + br * 2 * DD;
    float s = 0.f, q = 0.f;
    for (int k = 0; k < 128; k++) {
        s += part[k * DD + c];
        q += part[128 * DD + k * DD + c];
    }
    const float mean = s * (1.f / (float)MROWS);
    const float var  = q * (1.f / (float)MROWS) - mean * mean;
    const float scale = gamma[c] * rsqrtf(var + 1e-5f);
    statsOut[c]      = scale;
    statsOut[DD + c] = beta[c] - mean * scale;
}

// ---------------------------------------------------------------------------
// Combine: BN-apply + PReLU + residual + LayerNorm. grid = MROWS.
// ---------------------------------------------------------------------------
__global__ void combine_ln(const float* __restrict__ x,
                           const f16* __restrict__ yAll,
                           const float* __restrict__ stats,
                           const float* __restrict__ pa,
                           const float* __restrict__ pv,
                           const float* __restrict__ lng,
                           const float* __restrict__ lnb,
                           float* __restrict__ out)
{
    __shared__ float rs[8], rq[8];
    const int pos = blockIdx.x;
    const int b = pos >> 11, l = pos & 2047;
    const size_t yoff = (size_t)pos * DD;
    const size_t xoff = (size_t)l * (BB * DD) + (size_t)b * DD;
    const int t = threadIdx.x;
    const float aa = pa[0], av = pv[0];
    const f16* ya = yAll;
    const f16* yv = yAll + (size_t)MROWS * DD;

    float vv[3];
    float s = 0.f, q = 0.f;
#pragma unroll
    for (int j = 0; j < 3; j++) {
        const int d = t + j * 256;
        float va = __half2float(ya[yoff + d]) * stats[d] + stats[DD + d];
        va = va > 0.f ? va : aa * va;
        float vb = __half2float(yv[yoff + d]) * stats[2 * DD + d] + stats[3 * DD + d];
        vb = vb > 0.f ? vb : av * vb;
        float val = x[xoff + d] + va + vb;
        vv[j] = val; s += val; q += val * val;
    }
#pragma unroll
    for (int o = 16; o; o >>= 1) {
        s += __shfl_xor_sync(~0u, s, o);
        q += __shfl_xor_sync(~0u, q, o);
    }
    if ((t & 31) == 0) { rs[t >> 5] = s; rq[t >> 5] = q; }
    __syncthreads();
    s = 0.f; q = 0.f;
#pragma unroll
    for (int w = 0; w < 8; w++) { s += rs[w]; q += rq[w]; }
    const float mean = s * (1.f / (float)DD);
    const float var  = q * (1.f / (float)DD) - mean * mean;
    const float rstd = rsqrtf(var + 1e-5f);
#pragma unroll
    for (int j = 0; j < 3; j++) {
        const int d = t + j * 256;
        out[xoff + d] = (vv[j] - mean) * rstd * lng[d] + lnb[d];
    }
}

// ---------------------------------------------------------------------------
// Host orchestration (graph-capturable)
// ---------------------------------------------------------------------------
extern "C" void kernel_launch(void* const* d_in, const int* in_sizes, int n_in,
                              void* d_out, int out_size)
{
    const float* x_a    = (const float*)d_in[0];
    const float* x_v    = (const float*)d_in[1];
    const float* x      = (const float*)d_in[2];
    const float* W_a    = (const float*)d_in[3];
    const float* bn_a_g = (const float*)d_in[5];
    const float* bn_a_b = (const float*)d_in[6];
    const float* pre_a  = (const float*)d_in[7];
    const float* W_v    = (const float*)d_in[8];
    const float* bn_v_g = (const float*)d_in[10];
    const float* bn_v_b = (const float*)d_in[11];
    const float* pre_v  = (const float*)d_in[12];
    const float* ln_g   = (const float*)d_in[13];
    const float* ln_b   = (const float*)d_in[14];
    float* out = (float*)d_out;

    float *part, *stats, *rspart;
    f16 *S, *q, *kv, *kT, *c, *W, *y;
    cudaGetSymbolAddress((void**)&S,      g_S);
    cudaGetSymbolAddress((void**)&q,      g_q);
    cudaGetSymbolAddress((void**)&kv,     g_kv);
    cudaGetSymbolAddress((void**)&kT,     g_kT);
    cudaGetSymbolAddress((void**)&c,      g_c);
    cudaGetSymbolAddress((void**)&W,      g_W);
    cudaGetSymbolAddress((void**)&y,      g_y);
    cudaGetSymbolAddress((void**)&rspart, g_rspart);
    cudaGetSymbolAddress((void**)&part,   g_part);
    cudaGetSymbolAddress((void**)&stats,  g_stats);

    cudaFuncSetAttribute(mma_gemm<1>, cudaFuncAttributeMaxDynamicSharedMemorySize, GEMM_SMEM);
    cudaFuncSetAttribute(mma_gemm<2>, cudaFuncAttributeMaxDynamicSharedMemorySize, GEMM_SMEM);
    cudaFuncSetAttribute(mma_gemm<3>, cudaFuncAttributeMaxDynamicSharedMemorySize, GEMM_SMEM);

    // Prep: kv/kvT (z<16) + q (z>=16); W
    prep_all<<<dim3(DD / 32, LQ / 32, ZB + BB), dim3(32, 8)>>>(x_a, x_v, x, kv, kT, q);
    convert_w<<<dim3((DD * DD) / 256, 2), 256>>>(W_a, W_v, W);

    // GEMM1 + exp epilogue: S = exp(scale * q.kv), partial row sums
    mma_gemm<2><<<dim3(16, 16, ZB), GTHREADS, GEMM_SMEM>>>(
        q, kv, S, nullptr, rspart,
        DD, LQ, (long)LQ * DD, (long)LQ * DD, (long)LQ * LQ, QKSCALE, 7);

    // GEMM2 (narrow, 2 CTAs/SM): ctx = invsum * (S . kvT); inv computed in prologue
    mma_gemm<1><<<dim3(6, 16, ZB), GTHREADS, GEMM_SMEM>>>(
        S, kT, c, rspart, nullptr,
        LQ, DD, (long)LQ * LQ, (long)DD * LQ, (long)LQ * DD, 1.f, 0xFF);

    // GEMM3 + fused BN partials: y = ctx . W, partials into g_part
    mma_gemm<3><<<dim3(6, 128, 2), GTHREADS, GEMM_SMEM>>>(
        c, W, y, nullptr, part,
        DD, DD, (long)MROWS * DD, (long)DD * DD, (long)MROWS * DD, 1.f, 0xFF);

    bn_finalize<<<dim3(3, 2), 256>>>(part, bn_a_g, bn_a_b, bn_v_g, bn_v_b, stats);

    combine_ln<<<MROWS, 256>>>(x, y, stats, pre_a, pre_v, ln_g, ln_b, out);
}